// round 14
// baseline (speedup 1.0000x reference)
#include <cuda_runtime.h>
#include <cuda_fp16.h>
#include <cstdint>

// Problem constants
#define BATCH 4
#define CCH   256
#define NH    8
#define DH    32
#define NT    2304
#define O3    768
#define MT    256
#define KT    128
#define NTILE (NT / KT)    // 18

// Scratch (allocation-free rule: __device__ globals)
__device__ __half g_qh [BATCH * NH * NT * DH];  // fp16, scaled by dh^-.5*log2e
__device__ __half g_kh [BATCH * NH * NT * DH];
__device__ __half g_vh [BATCH * NH * NT * DH];
__device__ __half g_aoh[BATCH * NT * CCH];      // attention out, fp16
__device__ __half g_xh [BATCH * CCH * NT];      // x, fp16
__device__ __half g_wqh[O3 * CCH];              // w_qkv, fp16
__device__ __half g_wph[CCH * CCH];             // w_proj, fp16

__device__ __forceinline__ float ex2f(float x) {
    float r;
    asm("ex2.approx.f32 %0, %1;" : "=f"(r) : "f"(x));
    return r;
}
__device__ __forceinline__ uint32_t pack_h2(float lo, float hi) {
    uint32_t r;
    asm("cvt.rn.f16x2.f32 %0, %1, %2;" : "=r"(r) : "f"(hi), "f"(lo));
    return r;
}
__device__ __forceinline__ uint32_t smem_u32(const void* p) {
    uint32_t a;
    asm("{ .reg .u64 t; cvta.to.shared.u64 t, %1; cvt.u32.u64 %0, t; }" : "=r"(a) : "l"(p));
    return a;
}
__device__ __forceinline__ void cp16(uint32_t dst, const void* src) {
    asm volatile("cp.async.cg.shared.global [%0], [%1], 16;" :: "r"(dst), "l"(src));
}
#define CP_COMMIT() asm volatile("cp.async.commit_group;" ::: "memory")
#define CP_WAIT1()  asm volatile("cp.async.wait_group 1;" ::: "memory")

__device__ __forceinline__ void mma_f16(float c[4], const uint32_t a[4],
                                        uint32_t b0, uint32_t b1) {
    asm volatile(
        "mma.sync.aligned.m16n8k16.row.col.f32.f16.f16.f32 "
        "{%0,%1,%2,%3}, {%4,%5,%6,%7}, {%8,%9}, {%0,%1,%2,%3};"
        : "+f"(c[0]), "+f"(c[1]), "+f"(c[2]), "+f"(c[3])
        : "r"(a[0]), "r"(a[1]), "r"(a[2]), "r"(a[3]), "r"(b0), "r"(b1));
}
__device__ __forceinline__ void ldsm4t(uint32_t& r0, uint32_t& r1,
                                       uint32_t& r2, uint32_t& r3, uint32_t addr) {
    asm volatile(
        "ldmatrix.sync.aligned.m8n8.x4.trans.shared.b16 {%0,%1,%2,%3}, [%4];"
        : "=r"(r0), "=r"(r1), "=r"(r2), "=r"(r3) : "r"(addr));
}

// ---------------------------------------------------------------------------
// Kernel 0: prep — convert x, w_qkv, w_proj to fp16.
// ---------------------------------------------------------------------------
#define XN4 (BATCH * CCH * NT / 4)
#define WQ4 (O3 * CCH / 4)
#define WP4 (CCH * CCH / 4)

__global__ __launch_bounds__(256) void split_kernel(
    const float* __restrict__ x, const float* __restrict__ wq,
    const float* __restrict__ wp)
{
    int i = blockIdx.x * 256 + threadIdx.x;
    const float4* src;
    uint2* dst;
    int j;
    if (i < XN4)                  { src = (const float4*)x;  dst = (uint2*)g_xh;  j = i; }
    else if (i < XN4 + WQ4)       { src = (const float4*)wq; dst = (uint2*)g_wqh; j = i - XN4; }
    else if (i < XN4 + WQ4 + WP4) { src = (const float4*)wp; dst = (uint2*)g_wph; j = i - XN4 - WQ4; }
    else return;
    float4 f = src[j];
    dst[j] = make_uint2(pack_h2(f.x, f.y), pack_h2(f.z, f.w));
}

// ---------------------------------------------------------------------------
// Kernel 1: QKV projection, fp16 m16n8k16 GEMM, BK=64 (4 iters), cp.async
//   2-stage. A = x [k][m] staged, stride 136 halves, frags via
//   ldmatrix.x4.trans. B = w [n][k], stride 72 halves (36w+t4 distinct
//   mod 32 -> conflict-free), direct 32-bit frag loads.
//   Stage: A 64x136h (17408 B) + B 64x72h (9216 B) = 26624 B.
// ---------------------------------------------------------------------------
#define QKV_STAGE_B 26624
#define QKV_A_HALVES (64 * 136)

__global__ __launch_bounds__(256, 3) void qkv_tc_kernel(const float* __restrict__ bias)
{
    extern __shared__ __half sh[];
    const uint32_t sb = smem_u32(sh);

    const int b  = blockIdx.z;
    const int m0 = blockIdx.x * 128;
    const int o0 = blockIdx.y * 64;
    const int tid  = threadIdx.x;
    const int wid  = tid >> 5;
    const int lane = tid & 31;
    const int gq   = lane >> 2;
    const int t4   = lane & 3;
    const int wm   = wid & 3, wn = wid >> 2;

    // staging coords: A 64 rows x 128 halves (4 thr/row, 32 halves each);
    //                 B 64 rows x 64 halves (4 thr/row, 16 halves each)
    const int arow = tid >> 2, acol = (tid & 3) * 32;
    const int brow = tid >> 2, bcol = (tid & 3) * 16;

    const __half* xh = g_xh + (size_t)b * CCH * NT;
    const uint32_t a_off = (uint32_t)(arow * 136 + acol) * 2;
    const uint32_t b_off = (uint32_t)QKV_A_HALVES * 2 + (uint32_t)(brow * 72 + bcol) * 2;

    const int k_l = (lane & 7) + ((lane >> 4) << 3);
    const int m_l = ((lane >> 3) & 1) * 8;

    {
        const __half* as = xh + (size_t)arow * NT + m0 + acol;
        #pragma unroll
        for (int cv = 0; cv < 4; cv++) cp16(sb + a_off + cv * 16, as + cv * 8);
        const __half* bs = g_wqh + (size_t)(o0 + brow) * CCH + bcol;
        cp16(sb + b_off, bs);
        cp16(sb + b_off + 16, bs + 8);
    }
    CP_COMMIT();

    float c[2][4][4] = {};

    for (int it = 0; it < 4; it++) {
        if (it + 1 < 4) {
            const int k0 = (it + 1) * 64;
            const uint32_t base = sb + ((it + 1) & 1) * QKV_STAGE_B;
            const __half* as = xh + (size_t)(k0 + arow) * NT + m0 + acol;
            #pragma unroll
            for (int cv = 0; cv < 4; cv++) cp16(base + a_off + cv * 16, as + cv * 8);
            const __half* bs = g_wqh + (size_t)(o0 + brow) * CCH + k0 + bcol;
            cp16(base + b_off, bs);
            cp16(base + b_off + 16, bs + 8);
        }
        CP_COMMIT();
        CP_WAIT1();
        __syncthreads();

        const uint32_t Ab = sb + (it & 1) * QKV_STAGE_B;
        const __half* Bp = sh + ((it & 1) * QKV_STAGE_B) / 2 + QKV_A_HALVES;

        #pragma unroll
        for (int kc = 0; kc < 4; kc++) {
            uint32_t af[2][4];
            #pragma unroll
            for (int mt = 0; mt < 2; mt++) {
                uint32_t addr = Ab + (uint32_t)((kc * 16 + k_l) * 136
                                 + wm * 32 + mt * 16 + m_l) * 2;
                ldsm4t(af[mt][0], af[mt][1], af[mt][2], af[mt][3], addr);
            }
            #pragma unroll
            for (int nt = 0; nt < 4; nt++) {
                int n = wn * 32 + nt * 8 + gq;
                const __half* bp = Bp + n * 72 + kc * 16 + 2 * t4;
                uint32_t b0 = *(const uint32_t*)bp;
                uint32_t b1 = *(const uint32_t*)(bp + 8);
                mma_f16(c[0][nt], af[0], b0, b1);
                mma_f16(c[1][nt], af[1], b0, b1);
            }
        }
        __syncthreads();
    }

    // epilogue: bias; q scaled by dh^-0.5 * log2(e); fp16 outputs
    const float scale = 0.25503487f;
    #pragma unroll
    for (int mt = 0; mt < 2; mt++)
        #pragma unroll
        for (int nt = 0; nt < 4; nt++)
            #pragma unroll
            for (int i = 0; i < 4; i++) {
                int m = m0 + wm * 32 + mt * 16 + gq + ((i >= 2) ? 8 : 0);
                int o = o0 + wn * 32 + nt * 8 + 2 * t4 + (i & 1);
                float val = c[mt][nt][i] + __ldg(bias + o);
                int kind = o / CCH;
                int oc = o % CCH;
                int h = oc / DH, d = oc % DH;
                int idx = ((b * NH + h) * NT + m) * DH + d;
                if (kind == 0)
                    g_qh[idx] = __float2half_rn(val * scale);
                else if (kind == 1)
                    g_kh[idx] = __float2half_rn(val);
                else
                    g_vh[idx] = __float2half_rn(val);
            }
}

// ---------------------------------------------------------------------------
// Kernel 2: fp16 m16n8k16 flash attention, MT=256.
//   Row sums now on the (idle) fma pipe from the already-computed ex2 floats
//   — removes the 2 ones-MMAs per 16-key chunk (11% of the binding tensor
//   pipe). Final quad-shuffle reduction.
// ---------------------------------------------------------------------------
#define KSTR_H 40
#define STAGE_HALVES (2 * KT * KSTR_H)
#define ATT_STAGE_B  (STAGE_HALVES * 2)
#define ATT_SMEM     (2 * ATT_STAGE_B)

__global__ __launch_bounds__(256, 2) void attn_mma_kernel()
{
    extern __shared__ __half smh[];
    const uint32_t smbase = smem_u32(smh);

    const int bh   = blockIdx.y;
    const int n0   = blockIdx.x * MT;
    const int tid  = threadIdx.x;
    const int wid  = tid >> 5;
    const int lane = tid & 31;
    const int gq   = lane >> 2;
    const int t4   = lane & 3;
    const int r0   = wid * 32 + gq;

    const int srow = tid >> 1;
    const int shalf = tid & 1;
    const __half* kbase = g_kh + ((size_t)bh * NT + srow) * DH + shalf * 16;
    const __half* vbase = g_vh + ((size_t)bh * NT + srow) * DH + shalf * 16;
    const uint32_t kdst_off = (uint32_t)(srow * KSTR_H + shalf * 16) * 2;
    const uint32_t vdst_off = kdst_off + KT * KSTR_H * 2;

    const uint32_t lrow = lane & 15;
    const uint32_t lhof = (lane >> 4) * 8;

    uint32_t qa[2][2][4];
    #pragma unroll
    for (int mt = 0; mt < 2; mt++) {
        const __half* Q0 = g_qh + ((size_t)bh * NT + n0 + r0 + mt * 16) * DH;
        const __half* Q8 = Q0 + 8 * DH;
        #pragma unroll
        for (int kc = 0; kc < 2; kc++) {
            qa[mt][kc][0] = *(const uint32_t*)(Q0 + 2 * t4 + 16 * kc);
            qa[mt][kc][1] = *(const uint32_t*)(Q8 + 2 * t4 + 16 * kc);
            qa[mt][kc][2] = *(const uint32_t*)(Q0 + 2 * t4 + 8 + 16 * kc);
            qa[mt][kc][3] = *(const uint32_t*)(Q8 + 2 * t4 + 8 + 16 * kc);
        }
    }

    float o[2][4][4] = {};
    float la[2][2] = {};   // [mt][row-half] scalar row sums

    {
        #pragma unroll
        for (int cv = 0; cv < 2; cv++) {
            cp16(smbase + kdst_off + cv * 16, kbase + cv * 8);
            cp16(smbase + vdst_off + cv * 16, vbase + cv * 8);
        }
    }
    CP_COMMIT();

    for (int t = 0; t < NTILE; t++) {
        if (t + 1 < NTILE) {
            const uint32_t base = smbase + ((t + 1) & 1) * ATT_STAGE_B;
            const __half* ks = kbase + (size_t)(t + 1) * KT * DH;
            const __half* vs = vbase + (size_t)(t + 1) * KT * DH;
            #pragma unroll
            for (int cv = 0; cv < 2; cv++) {
                cp16(base + kdst_off + cv * 16, ks + cv * 8);
                cp16(base + vdst_off + cv * 16, vs + cv * 8);
            }
        }
        CP_COMMIT();
        CP_WAIT1();
        __syncthreads();

        const __half* Ksp = smh + (t & 1) * STAGE_HALVES;
        const uint32_t vsm = smbase + (t & 1) * ATT_STAGE_B + KT * KSTR_H * 2;

        #pragma unroll 2
        for (int c = 0; c < 8; c++) {
            uint32_t kb[2][2][2];
            #pragma unroll
            for (int g = 0; g < 2; g++) {
                const __half* kr = Ksp + (c * 16 + 8 * g + gq) * KSTR_H + 2 * t4;
                #pragma unroll
                for (int kc = 0; kc < 2; kc++) {
                    kb[g][kc][0] = *(const uint32_t*)(kr + 16 * kc);
                    kb[g][kc][1] = *(const uint32_t*)(kr + 16 * kc + 8);
                }
            }
            float s[2][2][4] = {};
            #pragma unroll
            for (int g = 0; g < 2; g++)
                #pragma unroll
                for (int mt = 0; mt < 2; mt++) {
                    mma_f16(s[g][mt], qa[mt][0], kb[g][0][0], kb[g][0][1]);
                    mma_f16(s[g][mt], qa[mt][1], kb[g][1][0], kb[g][1][1]);
                }
            uint32_t pa[2][4];
            #pragma unroll
            for (int mt = 0; mt < 2; mt++) {
                float e00 = ex2f(s[0][mt][0]), e01 = ex2f(s[0][mt][1]);
                float e02 = ex2f(s[0][mt][2]), e03 = ex2f(s[0][mt][3]);
                float e10 = ex2f(s[1][mt][0]), e11 = ex2f(s[1][mt][1]);
                float e12 = ex2f(s[1][mt][2]), e13 = ex2f(s[1][mt][3]);
                la[mt][0] += (e00 + e01) + (e10 + e11);
                la[mt][1] += (e02 + e03) + (e12 + e13);
                pa[mt][0] = pack_h2(e00, e01);
                pa[mt][1] = pack_h2(e02, e03);
                pa[mt][2] = pack_h2(e10, e11);
                pa[mt][3] = pack_h2(e12, e13);
            }
            uint32_t vb[4][2];
            uint32_t va = vsm + ((c * 16 + lrow) * KSTR_H + lhof) * 2;
            ldsm4t(vb[0][0], vb[0][1], vb[1][0], vb[1][1], va);
            ldsm4t(vb[2][0], vb[2][1], vb[3][0], vb[3][1], va + 32);
            #pragma unroll
            for (int mt = 0; mt < 2; mt++)
                #pragma unroll
                for (int db = 0; db < 4; db++)
                    mma_f16(o[mt][db], pa[mt], vb[db][0], vb[db][1]);
        }
        __syncthreads();
    }

    // quad-reduce row sums (cols within a row live across t4 lanes)
    #pragma unroll
    for (int mt = 0; mt < 2; mt++)
        #pragma unroll
        for (int rh = 0; rh < 2; rh++) {
            la[mt][rh] += __shfl_xor_sync(0xFFFFFFFFu, la[mt][rh], 1);
            la[mt][rh] += __shfl_xor_sync(0xFFFFFFFFu, la[mt][rh], 2);
        }

    // finalize: normalize; write g_aoh fp16
    const int b = bh >> 3, h = bh & 7;
    #pragma unroll
    for (int mt = 0; mt < 2; mt++) {
        float i0 = 1.f / la[mt][0];
        float i1 = 1.f / la[mt][1];
        size_t off0 = ((size_t)(b * NT) + n0 + r0 + mt * 16) * CCH + h * DH;
        size_t off8 = off0 + 8 * CCH;
        #pragma unroll
        for (int db = 0; db < 4; db++) {
            int d = db * 8 + 2 * t4;
            *(uint32_t*)(g_aoh + off0 + d) =
                pack_h2(o[mt][db][0] * i0, o[mt][db][1] * i0);
            *(uint32_t*)(g_aoh + off8 + d) =
                pack_h2(o[mt][db][2] * i1, o[mt][db][3] * i1);
        }
    }
}

// ---------------------------------------------------------------------------
// Kernel 3: output projection, fp16 m16n8k16 GEMM, BK=64 (4 iters).
//   A = g_aoh [m][k], B = w_proj [n][k], both stride 72 halves.
//   Stage: A 128x72h (18432 B) + B 64x72h (9216 B) = 27648 B.
// ---------------------------------------------------------------------------
#define PROJ_STAGE_B 27648
#define PROJ_A_HALVES (128 * 72)

__global__ __launch_bounds__(256, 3) void proj_tc_kernel(
    const float* __restrict__ bias, float* __restrict__ out)
{
    extern __shared__ __half ph[];
    const uint32_t sb = smem_u32(ph);

    const int b  = blockIdx.z;
    const int m0 = blockIdx.x * 128;
    const int o0 = blockIdx.y * 64;
    const int tid  = threadIdx.x;
    const int wid  = tid >> 5;
    const int lane = tid & 31;
    const int gq   = lane >> 2;
    const int t4   = lane & 3;
    const int wm   = wid & 3, wn = wid >> 2;

    const int arow = tid >> 1, acol = (tid & 1) * 32;   // A: 128 rows x 64 halves
    const int brow = tid >> 2, bcol = (tid & 3) * 16;   // B: 64 rows x 64 halves

    const __half* ag = g_aoh + (size_t)b * NT * CCH;
    const uint32_t a_off = (uint32_t)(arow * 72 + acol) * 2;
    const uint32_t b_off = (uint32_t)PROJ_A_HALVES * 2 + (uint32_t)(brow * 72 + bcol) * 2;

    {
        const __half* as = ag + (size_t)(m0 + arow) * CCH + acol;
        #pragma unroll
        for (int cv = 0; cv < 4; cv++) cp16(sb + a_off + cv * 16, as + cv * 8);
        const __half* bs = g_wph + (size_t)(o0 + brow) * CCH + bcol;
        cp16(sb + b_off, bs);
        cp16(sb + b_off + 16, bs + 8);
    }
    CP_COMMIT();

    float c[2][4][4] = {};

    for (int it = 0; it < 4; it++) {
        if (it + 1 < 4) {
            const int k0 = (it + 1) * 64;
            const uint32_t base = sb + ((it + 1) & 1) * PROJ_STAGE_B;
            const __half* as = ag + (size_t)(m0 + arow) * CCH + k0 + acol;
            #pragma unroll
            for (int cv = 0; cv < 4; cv++) cp16(base + a_off + cv * 16, as + cv * 8);
            const __half* bs = g_wph + (size_t)(o0 + brow) * CCH + k0 + bcol;
            cp16(base + b_off, bs);
            cp16(base + b_off + 16, bs + 8);
        }
        CP_COMMIT();
        CP_WAIT1();
        __syncthreads();

        const __half* Ap = ph + ((it & 1) * PROJ_STAGE_B) / 2;
        const __half* Bp = Ap + PROJ_A_HALVES;

        #pragma unroll
        for (int kc = 0; kc < 4; kc++) {
            uint32_t af[2][4];
            #pragma unroll
            for (int mt = 0; mt < 2; mt++) {
                int m = wm * 32 + mt * 16 + gq;
                const __half* ar = Ap + m * 72 + kc * 16 + 2 * t4;
                af[mt][0] = *(const uint32_t*)ar;
                af[mt][1] = *(const uint32_t*)(ar + 8 * 72);
                af[mt][2] = *(const uint32_t*)(ar + 8);
                af[mt][3] = *(const uint32_t*)(ar + 8 * 72 + 8);
            }
            #pragma unroll
            for (int nt = 0; nt < 4; nt++) {
                int n = wn * 32 + nt * 8 + gq;
                const __half* bp = Bp + n * 72 + kc * 16 + 2 * t4;
                uint32_t b0 = *(const uint32_t*)bp;
                uint32_t b1 = *(const uint32_t*)(bp + 8);
                mma_f16(c[0][nt], af[0], b0, b1);
                mma_f16(c[1][nt], af[1], b0, b1);
            }
        }
        __syncthreads();
    }

    #pragma unroll
    for (int mt = 0; mt < 2; mt++)
        #pragma unroll
        for (int nt = 0; nt < 4; nt++)
            #pragma unroll
            for (int i = 0; i < 4; i++) {
                int m = m0 + wm * 32 + mt * 16 + gq + ((i >= 2) ? 8 : 0);
                int o = o0 + wn * 32 + nt * 8 + 2 * t4 + (i & 1);
                out[(size_t)b * CCH * NT + (size_t)o * NT + m] =
                    c[mt][nt][i] + __ldg(bias + o);
            }
}

// ---------------------------------------------------------------------------
extern "C" void kernel_launch(void* const* d_in, const int* in_sizes, int n_in,
                              void* d_out, int out_size)
{
    (void)in_sizes; (void)n_in; (void)out_size;
    const float* x      = (const float*)d_in[0];
    const float* w_qkv  = (const float*)d_in[1];
    const float* b_qkv  = (const float*)d_in[2];
    const float* w_proj = (const float*)d_in[3];
    const float* b_proj = (const float*)d_in[4];
    float* out = (float*)d_out;

    cudaFuncSetAttribute(qkv_tc_kernel,
                         cudaFuncAttributeMaxDynamicSharedMemorySize,
                         2 * QKV_STAGE_B);
    cudaFuncSetAttribute(attn_mma_kernel,
                         cudaFuncAttributeMaxDynamicSharedMemorySize, ATT_SMEM);
    cudaFuncSetAttribute(proj_tc_kernel,
                         cudaFuncAttributeMaxDynamicSharedMemorySize,
                         2 * PROJ_STAGE_B);

    split_kernel<<<(XN4 + WQ4 + WP4 + 255) / 256, 256>>>(x, w_qkv, w_proj);

    dim3 g1(NT / 128, O3 / 64, BATCH);
    qkv_tc_kernel<<<g1, 256, 2 * QKV_STAGE_B>>>(b_qkv);

    dim3 g2(NT / MT, BATCH * NH);
    attn_mma_kernel<<<g2, 256, ATT_SMEM>>>();

    dim3 g3(NT / 128, CCH / 64, BATCH);
    proj_tc_kernel<<<g3, 256, 2 * PROJ_STAGE_B>>>(b_proj, out);
}

// round 15
// speedup vs baseline: 1.1149x; 1.1149x over previous
#include <cuda_runtime.h>
#include <cuda_fp16.h>
#include <cstdint>

// Problem constants
#define BATCH 4
#define CCH   256
#define NH    8
#define DH    32
#define NT    2304
#define O3    768
#define MT    256
#define KT    128
#define NTILE (NT / KT)    // 18

// Scratch (allocation-free rule: __device__ globals)
__device__ __half g_qh [BATCH * NH * NT * DH];  // fp16, scaled by dh^-.5*log2e
__device__ __half g_kh [BATCH * NH * NT * DH];
__device__ __half g_vh [BATCH * NH * NT * DH];
__device__ __half g_aoh[BATCH * NT * CCH];      // attention out, fp16
__device__ __half g_xh [BATCH * CCH * NT];      // x, fp16
__device__ __half g_wqh[O3 * CCH];              // w_qkv, fp16
__device__ __half g_wph[CCH * CCH];             // w_proj, fp16

__device__ __forceinline__ float ex2f(float x) {
    float r;
    asm("ex2.approx.f32 %0, %1;" : "=f"(r) : "f"(x));
    return r;
}
__device__ __forceinline__ uint32_t pack_h2(float lo, float hi) {
    uint32_t r;
    asm("cvt.rn.f16x2.f32 %0, %1, %2;" : "=r"(r) : "f"(hi), "f"(lo));
    return r;
}
__device__ __forceinline__ uint32_t smem_u32(const void* p) {
    uint32_t a;
    asm("{ .reg .u64 t; cvta.to.shared.u64 t, %1; cvt.u32.u64 %0, t; }" : "=r"(a) : "l"(p));
    return a;
}
__device__ __forceinline__ void cp16(uint32_t dst, const void* src) {
    asm volatile("cp.async.cg.shared.global [%0], [%1], 16;" :: "r"(dst), "l"(src));
}
#define CP_COMMIT() asm volatile("cp.async.commit_group;" ::: "memory")
#define CP_WAIT1()  asm volatile("cp.async.wait_group 1;" ::: "memory")
#define ONE_H2 0x3C003C00u

__device__ __forceinline__ void mma_f16(float c[4], const uint32_t a[4],
                                        uint32_t b0, uint32_t b1) {
    asm volatile(
        "mma.sync.aligned.m16n8k16.row.col.f32.f16.f16.f32 "
        "{%0,%1,%2,%3}, {%4,%5,%6,%7}, {%8,%9}, {%0,%1,%2,%3};"
        : "+f"(c[0]), "+f"(c[1]), "+f"(c[2]), "+f"(c[3])
        : "r"(a[0]), "r"(a[1]), "r"(a[2]), "r"(a[3]), "r"(b0), "r"(b1));
}
__device__ __forceinline__ void ldsm4t(uint32_t& r0, uint32_t& r1,
                                       uint32_t& r2, uint32_t& r3, uint32_t addr) {
    asm volatile(
        "ldmatrix.sync.aligned.m8n8.x4.trans.shared.b16 {%0,%1,%2,%3}, [%4];"
        : "=r"(r0), "=r"(r1), "=r"(r2), "=r"(r3) : "r"(addr));
}

// ---------------------------------------------------------------------------
// Kernel 0: prep — convert x, w_qkv, w_proj to fp16.
// ---------------------------------------------------------------------------
#define XN4 (BATCH * CCH * NT / 4)
#define WQ4 (O3 * CCH / 4)
#define WP4 (CCH * CCH / 4)

__global__ __launch_bounds__(256) void split_kernel(
    const float* __restrict__ x, const float* __restrict__ wq,
    const float* __restrict__ wp)
{
    int i = blockIdx.x * 256 + threadIdx.x;
    const float4* src;
    uint2* dst;
    int j;
    if (i < XN4)                  { src = (const float4*)x;  dst = (uint2*)g_xh;  j = i; }
    else if (i < XN4 + WQ4)       { src = (const float4*)wq; dst = (uint2*)g_wqh; j = i - XN4; }
    else if (i < XN4 + WQ4 + WP4) { src = (const float4*)wp; dst = (uint2*)g_wph; j = i - XN4 - WQ4; }
    else return;
    float4 f = src[j];
    dst[j] = make_uint2(pack_h2(f.x, f.y), pack_h2(f.z, f.w));
}

// ---------------------------------------------------------------------------
// Kernel 1: QKV projection, fp16 m16n8k16 GEMM, BK=32 (R13 config), cp.async
//   2-stage. Epilogue stores packed fp16 pairs.
//   Stage: A 32x136h (8704 B) + B 64x40h (5120 B) = 13824 B.
// ---------------------------------------------------------------------------
#define QKV_STAGE_B 13824

__global__ __launch_bounds__(256, 3) void qkv_tc_kernel(const float* __restrict__ bias)
{
    extern __shared__ __half sh[];
    const uint32_t sb = smem_u32(sh);

    const int b  = blockIdx.z;
    const int m0 = blockIdx.x * 128;
    const int o0 = blockIdx.y * 64;
    const int tid  = threadIdx.x;
    const int wid  = tid >> 5;
    const int lane = tid & 31;
    const int gq   = lane >> 2;
    const int t4   = lane & 3;
    const int wm   = wid & 3, wn = wid >> 2;

    const int arow = tid >> 3, acol = (tid & 7) * 16;   // A: 32 rows x 128 halves
    const int brow = tid >> 2, bcol = (tid & 3) * 8;    // B: 64 rows x 32 halves

    const __half* xh = g_xh + (size_t)b * CCH * NT;
    const uint32_t a_off = (uint32_t)(arow * 136 + acol) * 2;
    const uint32_t b_off = 8704u + (uint32_t)(brow * 40 + bcol) * 2;

    const int k_l = (lane & 7) + ((lane >> 4) << 3);
    const int m_l = ((lane >> 3) & 1) * 8;

    {
        const __half* as = xh + (size_t)arow * NT + m0 + acol;
        cp16(sb + a_off,      as);
        cp16(sb + a_off + 16, as + 8);
        cp16(sb + b_off, g_wqh + (size_t)(o0 + brow) * CCH + bcol);
    }
    CP_COMMIT();

    float c[2][4][4] = {};

    for (int it = 0; it < 8; it++) {
        if (it + 1 < 8) {
            const int k0 = (it + 1) * 32;
            const uint32_t base = sb + ((it + 1) & 1) * QKV_STAGE_B;
            const __half* as = xh + (size_t)(k0 + arow) * NT + m0 + acol;
            cp16(base + a_off,      as);
            cp16(base + a_off + 16, as + 8);
            cp16(base + b_off, g_wqh + (size_t)(o0 + brow) * CCH + k0 + bcol);
        }
        CP_COMMIT();
        CP_WAIT1();
        __syncthreads();

        const uint32_t Ab = sb + (it & 1) * QKV_STAGE_B;
        const __half* Bp = sh + ((it & 1) * QKV_STAGE_B + 8704) / 2;

        #pragma unroll
        for (int kc = 0; kc < 2; kc++) {
            uint32_t af[2][4];
            #pragma unroll
            for (int mt = 0; mt < 2; mt++) {
                uint32_t addr = Ab + (uint32_t)((kc * 16 + k_l) * 136
                                 + wm * 32 + mt * 16 + m_l) * 2;
                ldsm4t(af[mt][0], af[mt][1], af[mt][2], af[mt][3], addr);
            }
            #pragma unroll
            for (int nt = 0; nt < 4; nt++) {
                int n = wn * 32 + nt * 8 + gq;
                const __half* bp = Bp + n * 40 + kc * 16 + 2 * t4;
                uint32_t b0 = *(const uint32_t*)bp;
                uint32_t b1 = *(const uint32_t*)(bp + 8);
                mma_f16(c[0][nt], af[0], b0, b1);
                mma_f16(c[1][nt], af[1], b0, b1);
            }
        }
        __syncthreads();
    }

    // epilogue: bias; q scaled by dh^-0.5 * log2(e); packed fp16 pair stores
    const float scale = 0.25503487f;
    #pragma unroll
    for (int mt = 0; mt < 2; mt++)
        #pragma unroll
        for (int nt = 0; nt < 4; nt++) {
            int o = o0 + wn * 32 + nt * 8 + 2 * t4;      // even, pair (o, o+1)
            float2 bb = *(const float2*)(bias + o);
            int kind = o / CCH;
            int oc = o % CCH;
            int h = oc / DH, d = oc % DH;                // d even
            #pragma unroll
            for (int rh = 0; rh < 2; rh++) {
                int m = m0 + wm * 32 + mt * 16 + gq + rh * 8;
                float v0 = c[mt][nt][2 * rh]     + bb.x;
                float v1 = c[mt][nt][2 * rh + 1] + bb.y;
                int idx = ((b * NH + h) * NT + m) * DH + d;
                if (kind == 0)
                    *(uint32_t*)(g_qh + idx) = pack_h2(v0 * scale, v1 * scale);
                else if (kind == 1)
                    *(uint32_t*)(g_kh + idx) = pack_h2(v0, v1);
                else
                    *(uint32_t*)(g_vh + idx) = pack_h2(v0, v1);
            }
        }
}

// ---------------------------------------------------------------------------
// Kernel 2: fp16 m16n8k16 flash attention, MT=256, cp.async 3-stage pipeline
//   with a SINGLE __syncthreads per tile (staging t+2 after the barrier is
//   WAR-safe: all warps finished compute t-1 at that barrier). Ones-MMA row
//   sums retained (R14 showed scalar row sums hurt the issue budget).
// ---------------------------------------------------------------------------
#define KSTR_H 40
#define STAGE_HALVES (2 * KT * KSTR_H)        // 10240
#define ATT_STAGE_B  (STAGE_HALVES * 2)       // 20480 bytes
#define ATT_SMEM     (3 * ATT_STAGE_B)        // 61440 bytes

__global__ __launch_bounds__(256, 2) void attn_mma_kernel()
{
    extern __shared__ __half smh[];
    const uint32_t smbase = smem_u32(smh);

    const int bh   = blockIdx.y;
    const int n0   = blockIdx.x * MT;
    const int tid  = threadIdx.x;
    const int wid  = tid >> 5;
    const int lane = tid & 31;
    const int gq   = lane >> 2;
    const int t4   = lane & 3;
    const int r0   = wid * 32 + gq;

    const int srow = tid >> 1;
    const int shalf = tid & 1;
    const __half* kbase = g_kh + ((size_t)bh * NT + srow) * DH + shalf * 16;
    const __half* vbase = g_vh + ((size_t)bh * NT + srow) * DH + shalf * 16;
    const uint32_t kdst_off = (uint32_t)(srow * KSTR_H + shalf * 16) * 2;
    const uint32_t vdst_off = kdst_off + KT * KSTR_H * 2;

    const uint32_t lrow = lane & 15;
    const uint32_t lhof = (lane >> 4) * 8;

    uint32_t qa[2][2][4];
    #pragma unroll
    for (int mt = 0; mt < 2; mt++) {
        const __half* Q0 = g_qh + ((size_t)bh * NT + n0 + r0 + mt * 16) * DH;
        const __half* Q8 = Q0 + 8 * DH;
        #pragma unroll
        for (int kc = 0; kc < 2; kc++) {
            qa[mt][kc][0] = *(const uint32_t*)(Q0 + 2 * t4 + 16 * kc);
            qa[mt][kc][1] = *(const uint32_t*)(Q8 + 2 * t4 + 16 * kc);
            qa[mt][kc][2] = *(const uint32_t*)(Q0 + 2 * t4 + 8 + 16 * kc);
            qa[mt][kc][3] = *(const uint32_t*)(Q8 + 2 * t4 + 8 + 16 * kc);
        }
    }

    float o[2][4][4] = {};
    float la[2][4] = {};   // row sums via ones-MMA

    // prologue: stage tiles 0 and 1 into slots 0, 1
    #pragma unroll
    for (int pt = 0; pt < 2; pt++) {
        const uint32_t base = smbase + pt * ATT_STAGE_B;
        const __half* ks = kbase + (size_t)pt * KT * DH;
        const __half* vs = vbase + (size_t)pt * KT * DH;
        #pragma unroll
        for (int cv = 0; cv < 2; cv++) {
            cp16(base + kdst_off + cv * 16, ks + cv * 8);
            cp16(base + vdst_off + cv * 16, vs + cv * 8);
        }
        CP_COMMIT();
    }

    int sc = 2;   // staging slot for tile t+2
    int cc = 0;   // compute slot for tile t

    for (int t = 0; t < NTILE; t++) {
        CP_WAIT1();
        __syncthreads();

        if (t + 2 < NTILE) {
            const uint32_t base = smbase + sc * ATT_STAGE_B;
            const __half* ks = kbase + (size_t)(t + 2) * KT * DH;
            const __half* vs = vbase + (size_t)(t + 2) * KT * DH;
            #pragma unroll
            for (int cv = 0; cv < 2; cv++) {
                cp16(base + kdst_off + cv * 16, ks + cv * 8);
                cp16(base + vdst_off + cv * 16, vs + cv * 8);
            }
        }
        CP_COMMIT();

        const __half* Ksp = smh + cc * STAGE_HALVES;
        const uint32_t vsm = smbase + cc * ATT_STAGE_B + KT * KSTR_H * 2;

        #pragma unroll 2
        for (int c = 0; c < 8; c++) {
            uint32_t kb[2][2][2];
            #pragma unroll
            for (int g = 0; g < 2; g++) {
                const __half* kr = Ksp + (c * 16 + 8 * g + gq) * KSTR_H + 2 * t4;
                #pragma unroll
                for (int kc = 0; kc < 2; kc++) {
                    kb[g][kc][0] = *(const uint32_t*)(kr + 16 * kc);
                    kb[g][kc][1] = *(const uint32_t*)(kr + 16 * kc + 8);
                }
            }
            float s[2][2][4] = {};
            #pragma unroll
            for (int g = 0; g < 2; g++)
                #pragma unroll
                for (int mt = 0; mt < 2; mt++) {
                    mma_f16(s[g][mt], qa[mt][0], kb[g][0][0], kb[g][0][1]);
                    mma_f16(s[g][mt], qa[mt][1], kb[g][1][0], kb[g][1][1]);
                }
            uint32_t pa[2][4];
            #pragma unroll
            for (int mt = 0; mt < 2; mt++) {
                pa[mt][0] = pack_h2(ex2f(s[0][mt][0]), ex2f(s[0][mt][1]));
                pa[mt][1] = pack_h2(ex2f(s[0][mt][2]), ex2f(s[0][mt][3]));
                pa[mt][2] = pack_h2(ex2f(s[1][mt][0]), ex2f(s[1][mt][1]));
                pa[mt][3] = pack_h2(ex2f(s[1][mt][2]), ex2f(s[1][mt][3]));
            }
            mma_f16(la[0], pa[0], ONE_H2, ONE_H2);
            mma_f16(la[1], pa[1], ONE_H2, ONE_H2);
            uint32_t vb[4][2];
            uint32_t va = vsm + ((c * 16 + lrow) * KSTR_H + lhof) * 2;
            ldsm4t(vb[0][0], vb[0][1], vb[1][0], vb[1][1], va);
            ldsm4t(vb[2][0], vb[2][1], vb[3][0], vb[3][1], va + 32);
            #pragma unroll
            for (int mt = 0; mt < 2; mt++)
                #pragma unroll
                for (int db = 0; db < 4; db++)
                    mma_f16(o[mt][db], pa[mt], vb[db][0], vb[db][1]);
        }

        sc = (sc == 2) ? 0 : sc + 1;
        cc = (cc == 2) ? 0 : cc + 1;
    }

    // finalize: normalize by MMA row sums; write g_aoh fp16 pairs
    const int b = bh >> 3, h = bh & 7;
    #pragma unroll
    for (int mt = 0; mt < 2; mt++) {
        float i0 = 1.f / la[mt][0];
        float i1 = 1.f / la[mt][2];
        size_t off0 = ((size_t)(b * NT) + n0 + r0 + mt * 16) * CCH + h * DH;
        size_t off8 = off0 + 8 * CCH;
        #pragma unroll
        for (int db = 0; db < 4; db++) {
            int d = db * 8 + 2 * t4;
            *(uint32_t*)(g_aoh + off0 + d) =
                pack_h2(o[mt][db][0] * i0, o[mt][db][1] * i0);
            *(uint32_t*)(g_aoh + off8 + d) =
                pack_h2(o[mt][db][2] * i1, o[mt][db][3] * i1);
        }
    }
}

// ---------------------------------------------------------------------------
// Kernel 3: output projection, fp16 m16n8k16 GEMM, BK=32 (R13 config).
//   Stage: A 128x40h + B 64x40h = 15360 B.
// ---------------------------------------------------------------------------
#define PROJ_STAGE_B 15360

__global__ __launch_bounds__(256, 3) void proj_tc_kernel(
    const float* __restrict__ bias, float* __restrict__ out)
{
    extern __shared__ __half ph[];
    const uint32_t sb = smem_u32(ph);

    const int b  = blockIdx.z;
    const int m0 = blockIdx.x * 128;
    const int o0 = blockIdx.y * 64;
    const int tid  = threadIdx.x;
    const int wid  = tid >> 5;
    const int lane = tid & 31;
    const int gq   = lane >> 2;
    const int t4   = lane & 3;
    const int wm   = wid & 3, wn = wid >> 2;

    const int arow = tid >> 1, acol = (tid & 1) * 16;   // A: 128 rows x 32 halves
    const int brow = tid >> 2, bcol = (tid & 3) * 8;    // B: 64 rows x 32 halves

    const __half* ag = g_aoh + (size_t)b * NT * CCH;
    const uint32_t a_off = (uint32_t)(arow * 40 + acol) * 2;
    const uint32_t b_off = 10240u + (uint32_t)(brow * 40 + bcol) * 2;

    {
        const __half* as = ag + (size_t)(m0 + arow) * CCH + acol;
        cp16(sb + a_off,      as);
        cp16(sb + a_off + 16, as + 8);
        cp16(sb + b_off, g_wph + (size_t)(o0 + brow) * CCH + bcol);
    }
    CP_COMMIT();

    float c[2][4][4] = {};

    for (int it = 0; it < 8; it++) {
        if (it + 1 < 8) {
            const int k0 = (it + 1) * 32;
            const uint32_t base = sb + ((it + 1) & 1) * PROJ_STAGE_B;
            const __half* as = ag + (size_t)(m0 + arow) * CCH + k0 + acol;
            cp16(base + a_off,      as);
            cp16(base + a_off + 16, as + 8);
            cp16(base + b_off, g_wph + (size_t)(o0 + brow) * CCH + k0 + bcol);
        }
        CP_COMMIT();
        CP_WAIT1();
        __syncthreads();

        const __half* Ap = ph + ((it & 1) * PROJ_STAGE_B) / 2;
        const __half* Bp = Ap + 5120;

        #pragma unroll
        for (int kc = 0; kc < 2; kc++) {
            uint32_t af[2][4];
            #pragma unroll
            for (int mt = 0; mt < 2; mt++) {
                int m = wm * 32 + mt * 16 + gq;
                const __half* ar = Ap + m * 40 + kc * 16 + 2 * t4;
                af[mt][0] = *(const uint32_t*)ar;
                af[mt][1] = *(const uint32_t*)(ar + 8 * 40);
                af[mt][2] = *(const uint32_t*)(ar + 8);
                af[mt][3] = *(const uint32_t*)(ar + 8 * 40 + 8);
            }
            #pragma unroll
            for (int nt = 0; nt < 4; nt++) {
                int n = wn * 32 + nt * 8 + gq;
                const __half* bp = Bp + n * 40 + kc * 16 + 2 * t4;
                uint32_t b0 = *(const uint32_t*)bp;
                uint32_t b1 = *(const uint32_t*)(bp + 8);
                mma_f16(c[0][nt], af[0], b0, b1);
                mma_f16(c[1][nt], af[1], b0, b1);
            }
        }
        __syncthreads();
    }

    #pragma unroll
    for (int mt = 0; mt < 2; mt++)
        #pragma unroll
        for (int nt = 0; nt < 4; nt++)
            #pragma unroll
            for (int i = 0; i < 4; i++) {
                int m = m0 + wm * 32 + mt * 16 + gq + ((i >= 2) ? 8 : 0);
                int o = o0 + wn * 32 + nt * 8 + 2 * t4 + (i & 1);
                out[(size_t)b * CCH * NT + (size_t)o * NT + m] =
                    c[mt][nt][i] + __ldg(bias + o);
            }
}

// ---------------------------------------------------------------------------
extern "C" void kernel_launch(void* const* d_in, const int* in_sizes, int n_in,
                              void* d_out, int out_size)
{
    (void)in_sizes; (void)n_in; (void)out_size;
    const float* x      = (const float*)d_in[0];
    const float* w_qkv  = (const float*)d_in[1];
    const float* b_qkv  = (const float*)d_in[2];
    const float* w_proj = (const float*)d_in[3];
    const float* b_proj = (const float*)d_in[4];
    float* out = (float*)d_out;

    cudaFuncSetAttribute(qkv_tc_kernel,
                         cudaFuncAttributeMaxDynamicSharedMemorySize,
                         2 * QKV_STAGE_B);
    cudaFuncSetAttribute(attn_mma_kernel,
                         cudaFuncAttributeMaxDynamicSharedMemorySize, ATT_SMEM);
    cudaFuncSetAttribute(proj_tc_kernel,
                         cudaFuncAttributeMaxDynamicSharedMemorySize,
                         2 * PROJ_STAGE_B);

    split_kernel<<<(XN4 + WQ4 + WP4 + 255) / 256, 256>>>(x, w_qkv, w_proj);

    dim3 g1(NT / 128, O3 / 64, BATCH);
    qkv_tc_kernel<<<g1, 256, 2 * QKV_STAGE_B>>>(b_qkv);

    dim3 g2(NT / MT, BATCH * NH);
    attn_mma_kernel<<<g2, 256, ATT_SMEM>>>();

    dim3 g3(NT / 128, CCH / 64, BATCH);
    proj_tc_kernel<<<g3, 256, 2 * PROJ_STAGE_B>>>(b_proj, out);
}

// round 16
// speedup vs baseline: 1.1224x; 1.0067x over previous
#include <cuda_runtime.h>
#include <cuda_fp16.h>
#include <cstdint>

// Problem constants
#define BATCH 4
#define CCH   256
#define NH    8
#define DH    32
#define NT    2304
#define O3    768
#define MT    256
#define KT    128
#define NTILE (NT / KT)    // 18

// Scratch (allocation-free rule: __device__ globals)
__device__ __half g_qh [BATCH * NH * NT * DH];  // fp16, scaled by dh^-.5*log2e
__device__ __half g_kh [BATCH * NH * NT * DH];
__device__ __half g_vh [BATCH * NH * NT * DH];
__device__ __half g_aoh[BATCH * NT * CCH];      // attention out, fp16
__device__ __half g_xh [BATCH * CCH * NT];      // x, fp16
__device__ __half g_wqh[O3 * CCH];              // w_qkv, fp16
__device__ __half g_wph[CCH * CCH];             // w_proj, fp16

__device__ __forceinline__ float ex2f(float x) {
    float r;
    asm("ex2.approx.f32 %0, %1;" : "=f"(r) : "f"(x));
    return r;
}
__device__ __forceinline__ uint32_t pack_h2(float lo, float hi) {
    uint32_t r;
    asm("cvt.rn.f16x2.f32 %0, %1, %2;" : "=r"(r) : "f"(hi), "f"(lo));
    return r;
}
__device__ __forceinline__ uint32_t smem_u32(const void* p) {
    uint32_t a;
    asm("{ .reg .u64 t; cvta.to.shared.u64 t, %1; cvt.u32.u64 %0, t; }" : "=r"(a) : "l"(p));
    return a;
}
__device__ __forceinline__ void cp16(uint32_t dst, const void* src) {
    asm volatile("cp.async.cg.shared.global [%0], [%1], 16;" :: "r"(dst), "l"(src));
}
#define CP_COMMIT() asm volatile("cp.async.commit_group;" ::: "memory")
#define CP_WAIT1()  asm volatile("cp.async.wait_group 1;" ::: "memory")
#define ONE_H2 0x3C003C00u

__device__ __forceinline__ void mma_f16(float c[4], const uint32_t a[4],
                                        uint32_t b0, uint32_t b1) {
    asm volatile(
        "mma.sync.aligned.m16n8k16.row.col.f32.f16.f16.f32 "
        "{%0,%1,%2,%3}, {%4,%5,%6,%7}, {%8,%9}, {%0,%1,%2,%3};"
        : "+f"(c[0]), "+f"(c[1]), "+f"(c[2]), "+f"(c[3])
        : "r"(a[0]), "r"(a[1]), "r"(a[2]), "r"(a[3]), "r"(b0), "r"(b1));
}
__device__ __forceinline__ void ldsm4t(uint32_t& r0, uint32_t& r1,
                                       uint32_t& r2, uint32_t& r3, uint32_t addr) {
    asm volatile(
        "ldmatrix.sync.aligned.m8n8.x4.trans.shared.b16 {%0,%1,%2,%3}, [%4];"
        : "=r"(r0), "=r"(r1), "=r"(r2), "=r"(r3) : "r"(addr));
}

// ---------------------------------------------------------------------------
// Kernel 0: prep — convert x, w_qkv, w_proj to fp16.
// ---------------------------------------------------------------------------
#define XN4 (BATCH * CCH * NT / 4)
#define WQ4 (O3 * CCH / 4)
#define WP4 (CCH * CCH / 4)

__global__ __launch_bounds__(256) void split_kernel(
    const float* __restrict__ x, const float* __restrict__ wq,
    const float* __restrict__ wp)
{
    int i = blockIdx.x * 256 + threadIdx.x;
    const float4* src;
    uint2* dst;
    int j;
    if (i < XN4)                  { src = (const float4*)x;  dst = (uint2*)g_xh;  j = i; }
    else if (i < XN4 + WQ4)       { src = (const float4*)wq; dst = (uint2*)g_wqh; j = i - XN4; }
    else if (i < XN4 + WQ4 + WP4) { src = (const float4*)wp; dst = (uint2*)g_wph; j = i - XN4 - WQ4; }
    else return;
    float4 f = src[j];
    dst[j] = make_uint2(pack_h2(f.x, f.y), pack_h2(f.z, f.w));
}

// ---------------------------------------------------------------------------
// Kernel 1: QKV projection, fp16 m16n8k16 GEMM, BK=32, cp.async 3-stage
//   pipeline, ONE __syncthreads per iter (stage it+2 after barrier is
//   WAR-safe). Stage: A 32x136h (8704 B) + B 64x40h (5120 B) = 13824 B.
// ---------------------------------------------------------------------------
#define QKV_STAGE_B 13824

__global__ __launch_bounds__(256, 3) void qkv_tc_kernel(const float* __restrict__ bias)
{
    extern __shared__ __half sh[];
    const uint32_t sb = smem_u32(sh);

    const int b  = blockIdx.z;
    const int m0 = blockIdx.x * 128;
    const int o0 = blockIdx.y * 64;
    const int tid  = threadIdx.x;
    const int wid  = tid >> 5;
    const int lane = tid & 31;
    const int gq   = lane >> 2;
    const int t4   = lane & 3;
    const int wm   = wid & 3, wn = wid >> 2;

    const int arow = tid >> 3, acol = (tid & 7) * 16;   // A: 32 rows x 128 halves
    const int brow = tid >> 2, bcol = (tid & 3) * 8;    // B: 64 rows x 32 halves

    const __half* xh = g_xh + (size_t)b * CCH * NT;
    const uint32_t a_off = (uint32_t)(arow * 136 + acol) * 2;
    const uint32_t b_off = 8704u + (uint32_t)(brow * 40 + bcol) * 2;

    const int k_l = (lane & 7) + ((lane >> 4) << 3);
    const int m_l = ((lane >> 3) & 1) * 8;

    // prologue: stage iters 0 and 1 into slots 0, 1
    #pragma unroll
    for (int pt = 0; pt < 2; pt++) {
        const int k0 = pt * 32;
        const uint32_t base = sb + pt * QKV_STAGE_B;
        const __half* as = xh + (size_t)(k0 + arow) * NT + m0 + acol;
        cp16(base + a_off,      as);
        cp16(base + a_off + 16, as + 8);
        cp16(base + b_off, g_wqh + (size_t)(o0 + brow) * CCH + k0 + bcol);
        CP_COMMIT();
    }

    float c[2][4][4] = {};
    int sc = 2, cc = 0;

    for (int it = 0; it < 8; it++) {
        CP_WAIT1();
        __syncthreads();

        if (it + 2 < 8) {
            const int k0 = (it + 2) * 32;
            const uint32_t base = sb + sc * QKV_STAGE_B;
            const __half* as = xh + (size_t)(k0 + arow) * NT + m0 + acol;
            cp16(base + a_off,      as);
            cp16(base + a_off + 16, as + 8);
            cp16(base + b_off, g_wqh + (size_t)(o0 + brow) * CCH + k0 + bcol);
        }
        CP_COMMIT();

        const uint32_t Ab = sb + cc * QKV_STAGE_B;
        const __half* Bp = sh + (cc * QKV_STAGE_B + 8704) / 2;

        #pragma unroll
        for (int kc = 0; kc < 2; kc++) {
            uint32_t af[2][4];
            #pragma unroll
            for (int mt = 0; mt < 2; mt++) {
                uint32_t addr = Ab + (uint32_t)((kc * 16 + k_l) * 136
                                 + wm * 32 + mt * 16 + m_l) * 2;
                ldsm4t(af[mt][0], af[mt][1], af[mt][2], af[mt][3], addr);
            }
            #pragma unroll
            for (int nt = 0; nt < 4; nt++) {
                int n = wn * 32 + nt * 8 + gq;
                const __half* bp = Bp + n * 40 + kc * 16 + 2 * t4;
                uint32_t b0 = *(const uint32_t*)bp;
                uint32_t b1 = *(const uint32_t*)(bp + 8);
                mma_f16(c[0][nt], af[0], b0, b1);
                mma_f16(c[1][nt], af[1], b0, b1);
            }
        }

        sc = (sc == 2) ? 0 : sc + 1;
        cc = (cc == 2) ? 0 : cc + 1;
    }

    // epilogue: bias; q scaled by dh^-0.5 * log2(e); packed fp16 pair stores
    const float scale = 0.25503487f;
    #pragma unroll
    for (int mt = 0; mt < 2; mt++)
        #pragma unroll
        for (int nt = 0; nt < 4; nt++) {
            int o = o0 + wn * 32 + nt * 8 + 2 * t4;      // even, pair (o, o+1)
            float2 bb = *(const float2*)(bias + o);
            int kind = o / CCH;
            int oc = o % CCH;
            int h = oc / DH, d = oc % DH;                // d even
            #pragma unroll
            for (int rh = 0; rh < 2; rh++) {
                int m = m0 + wm * 32 + mt * 16 + gq + rh * 8;
                float v0 = c[mt][nt][2 * rh]     + bb.x;
                float v1 = c[mt][nt][2 * rh + 1] + bb.y;
                int idx = ((b * NH + h) * NT + m) * DH + d;
                if (kind == 0)
                    *(uint32_t*)(g_qh + idx) = pack_h2(v0 * scale, v1 * scale);
                else if (kind == 1)
                    *(uint32_t*)(g_kh + idx) = pack_h2(v0, v1);
                else
                    *(uint32_t*)(g_vh + idx) = pack_h2(v0, v1);
            }
        }
}

// ---------------------------------------------------------------------------
// Kernel 2: fp16 m16n8k16 flash attention, MT=256, cp.async 3-stage pipeline,
//   single __syncthreads per tile, ones-MMA row sums. (Unchanged from R15.)
// ---------------------------------------------------------------------------
#define KSTR_H 40
#define STAGE_HALVES (2 * KT * KSTR_H)        // 10240
#define ATT_STAGE_B  (STAGE_HALVES * 2)       // 20480 bytes
#define ATT_SMEM     (3 * ATT_STAGE_B)        // 61440 bytes

__global__ __launch_bounds__(256, 2) void attn_mma_kernel()
{
    extern __shared__ __half smh[];
    const uint32_t smbase = smem_u32(smh);

    const int bh   = blockIdx.y;
    const int n0   = blockIdx.x * MT;
    const int tid  = threadIdx.x;
    const int wid  = tid >> 5;
    const int lane = tid & 31;
    const int gq   = lane >> 2;
    const int t4   = lane & 3;
    const int r0   = wid * 32 + gq;

    const int srow = tid >> 1;
    const int shalf = tid & 1;
    const __half* kbase = g_kh + ((size_t)bh * NT + srow) * DH + shalf * 16;
    const __half* vbase = g_vh + ((size_t)bh * NT + srow) * DH + shalf * 16;
    const uint32_t kdst_off = (uint32_t)(srow * KSTR_H + shalf * 16) * 2;
    const uint32_t vdst_off = kdst_off + KT * KSTR_H * 2;

    const uint32_t lrow = lane & 15;
    const uint32_t lhof = (lane >> 4) * 8;

    uint32_t qa[2][2][4];
    #pragma unroll
    for (int mt = 0; mt < 2; mt++) {
        const __half* Q0 = g_qh + ((size_t)bh * NT + n0 + r0 + mt * 16) * DH;
        const __half* Q8 = Q0 + 8 * DH;
        #pragma unroll
        for (int kc = 0; kc < 2; kc++) {
            qa[mt][kc][0] = *(const uint32_t*)(Q0 + 2 * t4 + 16 * kc);
            qa[mt][kc][1] = *(const uint32_t*)(Q8 + 2 * t4 + 16 * kc);
            qa[mt][kc][2] = *(const uint32_t*)(Q0 + 2 * t4 + 8 + 16 * kc);
            qa[mt][kc][3] = *(const uint32_t*)(Q8 + 2 * t4 + 8 + 16 * kc);
        }
    }

    float o[2][4][4] = {};
    float la[2][4] = {};   // row sums via ones-MMA

    // prologue: stage tiles 0 and 1 into slots 0, 1
    #pragma unroll
    for (int pt = 0; pt < 2; pt++) {
        const uint32_t base = smbase + pt * ATT_STAGE_B;
        const __half* ks = kbase + (size_t)pt * KT * DH;
        const __half* vs = vbase + (size_t)pt * KT * DH;
        #pragma unroll
        for (int cv = 0; cv < 2; cv++) {
            cp16(base + kdst_off + cv * 16, ks + cv * 8);
            cp16(base + vdst_off + cv * 16, vs + cv * 8);
        }
        CP_COMMIT();
    }

    int sc = 2;   // staging slot for tile t+2
    int cc = 0;   // compute slot for tile t

    for (int t = 0; t < NTILE; t++) {
        CP_WAIT1();
        __syncthreads();

        if (t + 2 < NTILE) {
            const uint32_t base = smbase + sc * ATT_STAGE_B;
            const __half* ks = kbase + (size_t)(t + 2) * KT * DH;
            const __half* vs = vbase + (size_t)(t + 2) * KT * DH;
            #pragma unroll
            for (int cv = 0; cv < 2; cv++) {
                cp16(base + kdst_off + cv * 16, ks + cv * 8);
                cp16(base + vdst_off + cv * 16, vs + cv * 8);
            }
        }
        CP_COMMIT();

        const __half* Ksp = smh + cc * STAGE_HALVES;
        const uint32_t vsm = smbase + cc * ATT_STAGE_B + KT * KSTR_H * 2;

        #pragma unroll 2
        for (int c = 0; c < 8; c++) {
            uint32_t kb[2][2][2];
            #pragma unroll
            for (int g = 0; g < 2; g++) {
                const __half* kr = Ksp + (c * 16 + 8 * g + gq) * KSTR_H + 2 * t4;
                #pragma unroll
                for (int kc = 0; kc < 2; kc++) {
                    kb[g][kc][0] = *(const uint32_t*)(kr + 16 * kc);
                    kb[g][kc][1] = *(const uint32_t*)(kr + 16 * kc + 8);
                }
            }
            float s[2][2][4] = {};
            #pragma unroll
            for (int g = 0; g < 2; g++)
                #pragma unroll
                for (int mt = 0; mt < 2; mt++) {
                    mma_f16(s[g][mt], qa[mt][0], kb[g][0][0], kb[g][0][1]);
                    mma_f16(s[g][mt], qa[mt][1], kb[g][1][0], kb[g][1][1]);
                }
            uint32_t pa[2][4];
            #pragma unroll
            for (int mt = 0; mt < 2; mt++) {
                pa[mt][0] = pack_h2(ex2f(s[0][mt][0]), ex2f(s[0][mt][1]));
                pa[mt][1] = pack_h2(ex2f(s[0][mt][2]), ex2f(s[0][mt][3]));
                pa[mt][2] = pack_h2(ex2f(s[1][mt][0]), ex2f(s[1][mt][1]));
                pa[mt][3] = pack_h2(ex2f(s[1][mt][2]), ex2f(s[1][mt][3]));
            }
            mma_f16(la[0], pa[0], ONE_H2, ONE_H2);
            mma_f16(la[1], pa[1], ONE_H2, ONE_H2);
            uint32_t vb[4][2];
            uint32_t va = vsm + ((c * 16 + lrow) * KSTR_H + lhof) * 2;
            ldsm4t(vb[0][0], vb[0][1], vb[1][0], vb[1][1], va);
            ldsm4t(vb[2][0], vb[2][1], vb[3][0], vb[3][1], va + 32);
            #pragma unroll
            for (int mt = 0; mt < 2; mt++)
                #pragma unroll
                for (int db = 0; db < 4; db++)
                    mma_f16(o[mt][db], pa[mt], vb[db][0], vb[db][1]);
        }

        sc = (sc == 2) ? 0 : sc + 1;
        cc = (cc == 2) ? 0 : cc + 1;
    }

    // finalize: normalize by MMA row sums; write g_aoh fp16 pairs
    const int b = bh >> 3, h = bh & 7;
    #pragma unroll
    for (int mt = 0; mt < 2; mt++) {
        float i0 = 1.f / la[mt][0];
        float i1 = 1.f / la[mt][2];
        size_t off0 = ((size_t)(b * NT) + n0 + r0 + mt * 16) * CCH + h * DH;
        size_t off8 = off0 + 8 * CCH;
        #pragma unroll
        for (int db = 0; db < 4; db++) {
            int d = db * 8 + 2 * t4;
            *(uint32_t*)(g_aoh + off0 + d) =
                pack_h2(o[mt][db][0] * i0, o[mt][db][1] * i0);
            *(uint32_t*)(g_aoh + off8 + d) =
                pack_h2(o[mt][db][2] * i1, o[mt][db][3] * i1);
        }
    }
}

// ---------------------------------------------------------------------------
// Kernel 3: output projection, fp16 m16n8k16 GEMM, BK=32, cp.async 3-stage
//   pipeline, single sync per iter. Stage: A 128x40h + B 64x40h = 15360 B.
// ---------------------------------------------------------------------------
#define PROJ_STAGE_B 15360

__global__ __launch_bounds__(256, 3) void proj_tc_kernel(
    const float* __restrict__ bias, float* __restrict__ out)
{
    extern __shared__ __half ph[];
    const uint32_t sb = smem_u32(ph);

    const int b  = blockIdx.z;
    const int m0 = blockIdx.x * 128;
    const int o0 = blockIdx.y * 64;
    const int tid  = threadIdx.x;
    const int wid  = tid >> 5;
    const int lane = tid & 31;
    const int gq   = lane >> 2;
    const int t4   = lane & 3;
    const int wm   = wid & 3, wn = wid >> 2;

    const int arow = tid >> 1, acol = (tid & 1) * 16;   // A: 128 rows x 32 halves
    const int brow = tid >> 2, bcol = (tid & 3) * 8;    // B: 64 rows x 32 halves

    const __half* ag = g_aoh + (size_t)b * NT * CCH;
    const uint32_t a_off = (uint32_t)(arow * 40 + acol) * 2;
    const uint32_t b_off = 10240u + (uint32_t)(brow * 40 + bcol) * 2;

    // prologue: stage iters 0 and 1 into slots 0, 1
    #pragma unroll
    for (int pt = 0; pt < 2; pt++) {
        const int k0 = pt * 32;
        const uint32_t base = sb + pt * PROJ_STAGE_B;
        const __half* as = ag + (size_t)(m0 + arow) * CCH + k0 + acol;
        cp16(base + a_off,      as);
        cp16(base + a_off + 16, as + 8);
        cp16(base + b_off, g_wph + (size_t)(o0 + brow) * CCH + k0 + bcol);
        CP_COMMIT();
    }

    float c[2][4][4] = {};
    int sc = 2, cc = 0;

    for (int it = 0; it < 8; it++) {
        CP_WAIT1();
        __syncthreads();

        if (it + 2 < 8) {
            const int k0 = (it + 2) * 32;
            const uint32_t base = sb + sc * PROJ_STAGE_B;
            const __half* as = ag + (size_t)(m0 + arow) * CCH + k0 + acol;
            cp16(base + a_off,      as);
            cp16(base + a_off + 16, as + 8);
            cp16(base + b_off, g_wph + (size_t)(o0 + brow) * CCH + k0 + bcol);
        }
        CP_COMMIT();

        const __half* Ap = ph + (cc * PROJ_STAGE_B) / 2;
        const __half* Bp = Ap + 5120;

        #pragma unroll
        for (int kc = 0; kc < 2; kc++) {
            uint32_t af[2][4];
            #pragma unroll
            for (int mt = 0; mt < 2; mt++) {
                int m = wm * 32 + mt * 16 + gq;
                const __half* ar = Ap + m * 40 + kc * 16 + 2 * t4;
                af[mt][0] = *(const uint32_t*)ar;
                af[mt][1] = *(const uint32_t*)(ar + 8 * 40);
                af[mt][2] = *(const uint32_t*)(ar + 8);
                af[mt][3] = *(const uint32_t*)(ar + 8 * 40 + 8);
            }
            #pragma unroll
            for (int nt = 0; nt < 4; nt++) {
                int n = wn * 32 + nt * 8 + gq;
                const __half* bp = Bp + n * 40 + kc * 16 + 2 * t4;
                uint32_t b0 = *(const uint32_t*)bp;
                uint32_t b1 = *(const uint32_t*)(bp + 8);
                mma_f16(c[0][nt], af[0], b0, b1);
                mma_f16(c[1][nt], af[1], b0, b1);
            }
        }

        sc = (sc == 2) ? 0 : sc + 1;
        cc = (cc == 2) ? 0 : cc + 1;
    }

    #pragma unroll
    for (int mt = 0; mt < 2; mt++)
        #pragma unroll
        for (int nt = 0; nt < 4; nt++)
            #pragma unroll
            for (int i = 0; i < 4; i++) {
                int m = m0 + wm * 32 + mt * 16 + gq + ((i >= 2) ? 8 : 0);
                int o = o0 + wn * 32 + nt * 8 + 2 * t4 + (i & 1);
                out[(size_t)b * CCH * NT + (size_t)o * NT + m] =
                    c[mt][nt][i] + __ldg(bias + o);
            }
}

// ---------------------------------------------------------------------------
extern "C" void kernel_launch(void* const* d_in, const int* in_sizes, int n_in,
                              void* d_out, int out_size)
{
    (void)in_sizes; (void)n_in; (void)out_size;
    const float* x      = (const float*)d_in[0];
    const float* w_qkv  = (const float*)d_in[1];
    const float* b_qkv  = (const float*)d_in[2];
    const float* w_proj = (const float*)d_in[3];
    const float* b_proj = (const float*)d_in[4];
    float* out = (float*)d_out;

    cudaFuncSetAttribute(qkv_tc_kernel,
                         cudaFuncAttributeMaxDynamicSharedMemorySize,
                         3 * QKV_STAGE_B);
    cudaFuncSetAttribute(attn_mma_kernel,
                         cudaFuncAttributeMaxDynamicSharedMemorySize, ATT_SMEM);
    cudaFuncSetAttribute(proj_tc_kernel,
                         cudaFuncAttributeMaxDynamicSharedMemorySize,
                         3 * PROJ_STAGE_B);

    split_kernel<<<(XN4 + WQ4 + WP4 + 255) / 256, 256>>>(x, w_qkv, w_proj);

    dim3 g1(NT / 128, O3 / 64, BATCH);
    qkv_tc_kernel<<<g1, 256, 3 * QKV_STAGE_B>>>(b_qkv);

    dim3 g2(NT / MT, BATCH * NH);
    attn_mma_kernel<<<g2, 256, ATT_SMEM>>>();

    dim3 g3(NT / 128, CCH / 64, BATCH);
    proj_tc_kernel<<<g3, 256, 3 * PROJ_STAGE_B>>>(b_proj, out);
}

// round 17
// speedup vs baseline: 1.1705x; 1.0429x over previous
#include <cuda_runtime.h>
#include <cuda_fp16.h>
#include <cstdint>

// Problem constants
#define BATCH 4
#define CCH   256
#define NH    8
#define DH    32
#define NT    2304
#define O3    768
#define MT    256
#define KT    128
#define NTILE (NT / KT)    // 18

// Scratch (allocation-free rule: __device__ globals)
__device__ __half g_qh [BATCH * NH * NT * DH];  // fp16, scaled by dh^-.5*log2e
__device__ __half g_kh [BATCH * NH * NT * DH];
__device__ __half g_vh [BATCH * NH * NT * DH];
__device__ __half g_aoh[BATCH * NT * CCH];      // attention out, fp16
__device__ __half g_xh [BATCH * CCH * NT];      // x, fp16
__device__ __half g_wqh[O3 * CCH];              // w_qkv, fp16
__device__ __half g_wph[CCH * CCH];             // w_proj, fp16

__device__ __forceinline__ float ex2f(float x) {
    float r;
    asm("ex2.approx.f32 %0, %1;" : "=f"(r) : "f"(x));
    return r;
}
__device__ __forceinline__ uint32_t pack_h2(float lo, float hi) {
    uint32_t r;
    asm("cvt.rn.f16x2.f32 %0, %1, %2;" : "=r"(r) : "f"(hi), "f"(lo));
    return r;
}
__device__ __forceinline__ uint32_t smem_u32(const void* p) {
    uint32_t a;
    asm("{ .reg .u64 t; cvta.to.shared.u64 t, %1; cvt.u32.u64 %0, t; }" : "=r"(a) : "l"(p));
    return a;
}
__device__ __forceinline__ void cp16(uint32_t dst, const void* src) {
    asm volatile("cp.async.cg.shared.global [%0], [%1], 16;" :: "r"(dst), "l"(src));
}
#define CP_COMMIT() asm volatile("cp.async.commit_group;" ::: "memory")
#define CP_WAIT1()  asm volatile("cp.async.wait_group 1;" ::: "memory")
#define ONE_H2 0x3C003C00u

__device__ __forceinline__ void mma_f16(float c[4], const uint32_t a[4],
                                        uint32_t b0, uint32_t b1) {
    asm volatile(
        "mma.sync.aligned.m16n8k16.row.col.f32.f16.f16.f32 "
        "{%0,%1,%2,%3}, {%4,%5,%6,%7}, {%8,%9}, {%0,%1,%2,%3};"
        : "+f"(c[0]), "+f"(c[1]), "+f"(c[2]), "+f"(c[3])
        : "r"(a[0]), "r"(a[1]), "r"(a[2]), "r"(a[3]), "r"(b0), "r"(b1));
}
__device__ __forceinline__ void ldsm4t(uint32_t& r0, uint32_t& r1,
                                       uint32_t& r2, uint32_t& r3, uint32_t addr) {
    asm volatile(
        "ldmatrix.sync.aligned.m8n8.x4.trans.shared.b16 {%0,%1,%2,%3}, [%4];"
        : "=r"(r0), "=r"(r1), "=r"(r2), "=r"(r3) : "r"(addr));
}
__device__ __forceinline__ void ldsm4(uint32_t& r0, uint32_t& r1,
                                      uint32_t& r2, uint32_t& r3, uint32_t addr) {
    asm volatile(
        "ldmatrix.sync.aligned.m8n8.x4.shared.b16 {%0,%1,%2,%3}, [%4];"
        : "=r"(r0), "=r"(r1), "=r"(r2), "=r"(r3) : "r"(addr));
}

// ---------------------------------------------------------------------------
// Kernel 0: prep — convert x, w_qkv, w_proj to fp16.
// ---------------------------------------------------------------------------
#define XN4 (BATCH * CCH * NT / 4)
#define WQ4 (O3 * CCH / 4)
#define WP4 (CCH * CCH / 4)

__global__ __launch_bounds__(256) void split_kernel(
    const float* __restrict__ x, const float* __restrict__ wq,
    const float* __restrict__ wp)
{
    int i = blockIdx.x * 256 + threadIdx.x;
    const float4* src;
    uint2* dst;
    int j;
    if (i < XN4)                  { src = (const float4*)x;  dst = (uint2*)g_xh;  j = i; }
    else if (i < XN4 + WQ4)       { src = (const float4*)wq; dst = (uint2*)g_wqh; j = i - XN4; }
    else if (i < XN4 + WQ4 + WP4) { src = (const float4*)wp; dst = (uint2*)g_wph; j = i - XN4 - WQ4; }
    else return;
    float4 f = src[j];
    dst[j] = make_uint2(pack_h2(f.x, f.y), pack_h2(f.z, f.w));
}

// ---------------------------------------------------------------------------
// Kernel 1: QKV projection, fp16 m16n8k16 GEMM, BK=32, cp.async 3-stage
//   pipeline, one sync/iter. B-frags now via ldmatrix.x4 (2 per kc, replaces
//   8 LDS.32). Stage: A 32x136h (8704 B) + B 64x40h (5120 B) = 13824 B.
// ---------------------------------------------------------------------------
#define QKV_STAGE_B 13824

__global__ __launch_bounds__(256, 3) void qkv_tc_kernel(const float* __restrict__ bias)
{
    extern __shared__ __half sh[];
    const uint32_t sb = smem_u32(sh);

    const int b  = blockIdx.z;
    const int m0 = blockIdx.x * 128;
    const int o0 = blockIdx.y * 64;
    const int tid  = threadIdx.x;
    const int wid  = tid >> 5;
    const int lane = tid & 31;
    const int gq   = lane >> 2;
    const int t4   = lane & 3;
    const int wm   = wid & 3, wn = wid >> 2;

    const int arow = tid >> 3, acol = (tid & 7) * 16;   // A: 32 rows x 128 halves
    const int brow = tid >> 2, bcol = (tid & 3) * 8;    // B: 64 rows x 32 halves

    const __half* xh = g_xh + (size_t)b * CCH * NT;
    const uint32_t a_off = (uint32_t)(arow * 136 + acol) * 2;
    const uint32_t b_off = 8704u + (uint32_t)(brow * 40 + bcol) * 2;

    // ldmatrix lane pieces (A, trans): k/m within tile
    const int k_l = (lane & 7) + ((lane >> 4) << 3);
    const int m_l = ((lane >> 3) & 1) * 8;
    // ldmatrix lane pieces (B, non-trans n8k16): row = n, col = k-half
    const int brow_l = (lane & 7) + ((lane >> 4) << 3);   // +8 rows -> nt odd
    const int bcol_l = ((lane >> 3) & 1) * 8;             // +8 cols -> b1

    // prologue: stage iters 0 and 1 into slots 0, 1
    #pragma unroll
    for (int pt = 0; pt < 2; pt++) {
        const int k0 = pt * 32;
        const uint32_t base = sb + pt * QKV_STAGE_B;
        const __half* as = xh + (size_t)(k0 + arow) * NT + m0 + acol;
        cp16(base + a_off,      as);
        cp16(base + a_off + 16, as + 8);
        cp16(base + b_off, g_wqh + (size_t)(o0 + brow) * CCH + k0 + bcol);
        CP_COMMIT();
    }

    float c[2][4][4] = {};
    int sc = 2, cc = 0;

    for (int it = 0; it < 8; it++) {
        CP_WAIT1();
        __syncthreads();

        if (it + 2 < 8) {
            const int k0 = (it + 2) * 32;
            const uint32_t base = sb + sc * QKV_STAGE_B;
            const __half* as = xh + (size_t)(k0 + arow) * NT + m0 + acol;
            cp16(base + a_off,      as);
            cp16(base + a_off + 16, as + 8);
            cp16(base + b_off, g_wqh + (size_t)(o0 + brow) * CCH + k0 + bcol);
        }
        CP_COMMIT();

        const uint32_t Ab = sb + cc * QKV_STAGE_B;
        const uint32_t Bb = Ab + 8704u;

        #pragma unroll
        for (int kc = 0; kc < 2; kc++) {
            uint32_t af[2][4];
            #pragma unroll
            for (int mt = 0; mt < 2; mt++) {
                uint32_t addr = Ab + (uint32_t)((kc * 16 + k_l) * 136
                                 + wm * 32 + mt * 16 + m_l) * 2;
                ldsm4t(af[mt][0], af[mt][1], af[mt][2], af[mt][3], addr);
            }
            // B frags: 2 x ldmatrix.x4 -> (nt0 b0,b1, nt1 b0,b1), (nt2.., nt3..)
            uint32_t bf[8];
            uint32_t ba = Bb + (uint32_t)((wn * 32 + brow_l) * 40 + kc * 16 + bcol_l) * 2;
            ldsm4(bf[0], bf[1], bf[2], bf[3], ba);
            ldsm4(bf[4], bf[5], bf[6], bf[7], ba + 16 * 40 * 2);
            #pragma unroll
            for (int nt = 0; nt < 4; nt++) {
                mma_f16(c[0][nt], af[0], bf[2 * nt], bf[2 * nt + 1]);
                mma_f16(c[1][nt], af[1], bf[2 * nt], bf[2 * nt + 1]);
            }
        }

        sc = (sc == 2) ? 0 : sc + 1;
        cc = (cc == 2) ? 0 : cc + 1;
    }

    // epilogue: bias; q scaled by dh^-0.5 * log2(e); packed fp16 pair stores
    const float scale = 0.25503487f;
    #pragma unroll
    for (int mt = 0; mt < 2; mt++)
        #pragma unroll
        for (int nt = 0; nt < 4; nt++) {
            int o = o0 + wn * 32 + nt * 8 + 2 * t4;      // even, pair (o, o+1)
            float2 bb = *(const float2*)(bias + o);
            int kind = o / CCH;
            int oc = o % CCH;
            int h = oc / DH, d = oc % DH;                // d even
            #pragma unroll
            for (int rh = 0; rh < 2; rh++) {
                int m = m0 + wm * 32 + mt * 16 + gq + rh * 8;
                float v0 = c[mt][nt][2 * rh]     + bb.x;
                float v1 = c[mt][nt][2 * rh + 1] + bb.y;
                int idx = ((b * NH + h) * NT + m) * DH + d;
                if (kind == 0)
                    *(uint32_t*)(g_qh + idx) = pack_h2(v0 * scale, v1 * scale);
                else if (kind == 1)
                    *(uint32_t*)(g_kh + idx) = pack_h2(v0, v1);
                else
                    *(uint32_t*)(g_vh + idx) = pack_h2(v0, v1);
            }
        }
}

// ---------------------------------------------------------------------------
// Kernel 2: fp16 m16n8k16 flash attention, MT=256, cp.async 3-stage pipeline,
//   single sync/tile, ones-MMA row sums. K-frags now via ldmatrix.x4
//   (2 per chunk, replaces 8 LDS.32).
// ---------------------------------------------------------------------------
#define KSTR_H 40
#define STAGE_HALVES (2 * KT * KSTR_H)        // 10240
#define ATT_STAGE_B  (STAGE_HALVES * 2)       // 20480 bytes
#define ATT_SMEM     (3 * ATT_STAGE_B)        // 61440 bytes

__global__ __launch_bounds__(256, 2) void attn_mma_kernel()
{
    extern __shared__ __half smh[];
    const uint32_t smbase = smem_u32(smh);

    const int bh   = blockIdx.y;
    const int n0   = blockIdx.x * MT;
    const int tid  = threadIdx.x;
    const int wid  = tid >> 5;
    const int lane = tid & 31;
    const int gq   = lane >> 2;
    const int t4   = lane & 3;
    const int r0   = wid * 32 + gq;

    const int srow = tid >> 1;
    const int shalf = tid & 1;
    const __half* kbase = g_kh + ((size_t)bh * NT + srow) * DH + shalf * 16;
    const __half* vbase = g_vh + ((size_t)bh * NT + srow) * DH + shalf * 16;
    const uint32_t kdst_off = (uint32_t)(srow * KSTR_H + shalf * 16) * 2;
    const uint32_t vdst_off = kdst_off + KT * KSTR_H * 2;

    // V ldmatrix lane pieces (trans)
    const uint32_t lrow = lane & 15;
    const uint32_t lhof = (lane >> 4) * 8;
    // K ldmatrix lane pieces (non-trans): row-in-chunk, k-half
    const int krow_l = (lane & 7) + ((lane >> 4) << 3);   // +8 -> group 1
    const int kcol_l = ((lane >> 3) & 1) * 8;             // +8 halves -> b1

    uint32_t qa[2][2][4];
    #pragma unroll
    for (int mt = 0; mt < 2; mt++) {
        const __half* Q0 = g_qh + ((size_t)bh * NT + n0 + r0 + mt * 16) * DH;
        const __half* Q8 = Q0 + 8 * DH;
        #pragma unroll
        for (int kc = 0; kc < 2; kc++) {
            qa[mt][kc][0] = *(const uint32_t*)(Q0 + 2 * t4 + 16 * kc);
            qa[mt][kc][1] = *(const uint32_t*)(Q8 + 2 * t4 + 16 * kc);
            qa[mt][kc][2] = *(const uint32_t*)(Q0 + 2 * t4 + 8 + 16 * kc);
            qa[mt][kc][3] = *(const uint32_t*)(Q8 + 2 * t4 + 8 + 16 * kc);
        }
    }

    float o[2][4][4] = {};
    float la[2][4] = {};   // row sums via ones-MMA

    // prologue: stage tiles 0 and 1 into slots 0, 1
    #pragma unroll
    for (int pt = 0; pt < 2; pt++) {
        const uint32_t base = smbase + pt * ATT_STAGE_B;
        const __half* ks = kbase + (size_t)pt * KT * DH;
        const __half* vs = vbase + (size_t)pt * KT * DH;
        #pragma unroll
        for (int cv = 0; cv < 2; cv++) {
            cp16(base + kdst_off + cv * 16, ks + cv * 8);
            cp16(base + vdst_off + cv * 16, vs + cv * 8);
        }
        CP_COMMIT();
    }

    int sc = 2;   // staging slot for tile t+2
    int cc = 0;   // compute slot for tile t

    for (int t = 0; t < NTILE; t++) {
        CP_WAIT1();
        __syncthreads();

        if (t + 2 < NTILE) {
            const uint32_t base = smbase + sc * ATT_STAGE_B;
            const __half* ks = kbase + (size_t)(t + 2) * KT * DH;
            const __half* vs = vbase + (size_t)(t + 2) * KT * DH;
            #pragma unroll
            for (int cv = 0; cv < 2; cv++) {
                cp16(base + kdst_off + cv * 16, ks + cv * 8);
                cp16(base + vdst_off + cv * 16, vs + cv * 8);
            }
        }
        CP_COMMIT();

        const uint32_t ksm = smbase + cc * ATT_STAGE_B;
        const uint32_t vsm = ksm + KT * KSTR_H * 2;

        #pragma unroll 2
        for (int c = 0; c < 8; c++) {
            // K frags: 2 x ldmatrix.x4 -> (g0 b0,b1, g1 b0,b1) per kc
            uint32_t kf0[4], kf1[4];
            uint32_t ka = ksm + (uint32_t)((c * 16 + krow_l) * KSTR_H + kcol_l) * 2;
            ldsm4(kf0[0], kf0[1], kf0[2], kf0[3], ka);        // kc = 0
            ldsm4(kf1[0], kf1[1], kf1[2], kf1[3], ka + 32);   // kc = 1 (+16 halves)

            float s[2][2][4] = {};
            #pragma unroll
            for (int mt = 0; mt < 2; mt++) {
                mma_f16(s[0][mt], qa[mt][0], kf0[0], kf0[1]);
                mma_f16(s[1][mt], qa[mt][0], kf0[2], kf0[3]);
                mma_f16(s[0][mt], qa[mt][1], kf1[0], kf1[1]);
                mma_f16(s[1][mt], qa[mt][1], kf1[2], kf1[3]);
            }
            uint32_t pa[2][4];
            #pragma unroll
            for (int mt = 0; mt < 2; mt++) {
                pa[mt][0] = pack_h2(ex2f(s[0][mt][0]), ex2f(s[0][mt][1]));
                pa[mt][1] = pack_h2(ex2f(s[0][mt][2]), ex2f(s[0][mt][3]));
                pa[mt][2] = pack_h2(ex2f(s[1][mt][0]), ex2f(s[1][mt][1]));
                pa[mt][3] = pack_h2(ex2f(s[1][mt][2]), ex2f(s[1][mt][3]));
            }
            mma_f16(la[0], pa[0], ONE_H2, ONE_H2);
            mma_f16(la[1], pa[1], ONE_H2, ONE_H2);
            uint32_t vb[4][2];
            uint32_t va = vsm + ((c * 16 + lrow) * KSTR_H + lhof) * 2;
            ldsm4t(vb[0][0], vb[0][1], vb[1][0], vb[1][1], va);
            ldsm4t(vb[2][0], vb[2][1], vb[3][0], vb[3][1], va + 32);
            #pragma unroll
            for (int mt = 0; mt < 2; mt++)
                #pragma unroll
                for (int db = 0; db < 4; db++)
                    mma_f16(o[mt][db], pa[mt], vb[db][0], vb[db][1]);
        }

        sc = (sc == 2) ? 0 : sc + 1;
        cc = (cc == 2) ? 0 : cc + 1;
    }

    // finalize: normalize by MMA row sums; write g_aoh fp16 pairs
    const int b = bh >> 3, h = bh & 7;
    #pragma unroll
    for (int mt = 0; mt < 2; mt++) {
        float i0 = 1.f / la[mt][0];
        float i1 = 1.f / la[mt][2];
        size_t off0 = ((size_t)(b * NT) + n0 + r0 + mt * 16) * CCH + h * DH;
        size_t off8 = off0 + 8 * CCH;
        #pragma unroll
        for (int db = 0; db < 4; db++) {
            int d = db * 8 + 2 * t4;
            *(uint32_t*)(g_aoh + off0 + d) =
                pack_h2(o[mt][db][0] * i0, o[mt][db][1] * i0);
            *(uint32_t*)(g_aoh + off8 + d) =
                pack_h2(o[mt][db][2] * i1, o[mt][db][3] * i1);
        }
    }
}

// ---------------------------------------------------------------------------
// Kernel 3: output projection, fp16 m16n8k16 GEMM, BK=32, cp.async 3-stage
//   pipeline, single sync/iter. A- and B-frags via ldmatrix.x4
//   (8 LDSM/iter replaces 32 LDS.32). Stage: A 128x40h + B 64x40h = 15360 B.
// ---------------------------------------------------------------------------
#define PROJ_STAGE_B 15360

__global__ __launch_bounds__(256, 3) void proj_tc_kernel(
    const float* __restrict__ bias, float* __restrict__ out)
{
    extern __shared__ __half ph[];
    const uint32_t sb = smem_u32(ph);

    const int b  = blockIdx.z;
    const int m0 = blockIdx.x * 128;
    const int o0 = blockIdx.y * 64;
    const int tid  = threadIdx.x;
    const int wid  = tid >> 5;
    const int lane = tid & 31;
    const int gq   = lane >> 2;
    const int t4   = lane & 3;
    const int wm   = wid & 3, wn = wid >> 2;

    const int arow = tid >> 1, acol = (tid & 1) * 16;   // A: 128 rows x 32 halves
    const int brow = tid >> 2, bcol = (tid & 3) * 8;    // B: 64 rows x 32 halves

    const __half* ag = g_aoh + (size_t)b * NT * CCH;
    const uint32_t a_off = (uint32_t)(arow * 40 + acol) * 2;
    const uint32_t b_off = 10240u + (uint32_t)(brow * 40 + bcol) * 2;

    // ldmatrix lane pieces: A (m16 frag): row/col; B (n8 frag): row/col
    const int arow_l = (lane & 7) + (((lane >> 3) & 1) << 3);  // +8 -> a1/a3
    const int acol_l = (lane >> 4) * 8;                        // +8 -> a2/a3
    const int brow_l = (lane & 7) + ((lane >> 4) << 3);        // +8 -> nt odd
    const int bcol_l = ((lane >> 3) & 1) * 8;                  // +8 -> b1

    // prologue: stage iters 0 and 1 into slots 0, 1
    #pragma unroll
    for (int pt = 0; pt < 2; pt++) {
        const int k0 = pt * 32;
        const uint32_t base = sb + pt * PROJ_STAGE_B;
        const __half* as = ag + (size_t)(m0 + arow) * CCH + k0 + acol;
        cp16(base + a_off,      as);
        cp16(base + a_off + 16, as + 8);
        cp16(base + b_off, g_wph + (size_t)(o0 + brow) * CCH + k0 + bcol);
        CP_COMMIT();
    }

    float c[2][4][4] = {};
    int sc = 2, cc = 0;

    for (int it = 0; it < 8; it++) {
        CP_WAIT1();
        __syncthreads();

        if (it + 2 < 8) {
            const int k0 = (it + 2) * 32;
            const uint32_t base = sb + sc * PROJ_STAGE_B;
            const __half* as = ag + (size_t)(m0 + arow) * CCH + k0 + acol;
            cp16(base + a_off,      as);
            cp16(base + a_off + 16, as + 8);
            cp16(base + b_off, g_wph + (size_t)(o0 + brow) * CCH + k0 + bcol);
        }
        CP_COMMIT();

        const uint32_t Ab = sb + cc * PROJ_STAGE_B;
        const uint32_t Bb = Ab + 10240u;

        #pragma unroll
        for (int kc = 0; kc < 2; kc++) {
            uint32_t af[2][4];
            #pragma unroll
            for (int mt = 0; mt < 2; mt++) {
                uint32_t aa = Ab + (uint32_t)((wm * 32 + mt * 16 + arow_l) * 40
                               + kc * 16 + acol_l) * 2;
                ldsm4(af[mt][0], af[mt][1], af[mt][2], af[mt][3], aa);
            }
            uint32_t bf[8];
            uint32_t ba = Bb + (uint32_t)((wn * 32 + brow_l) * 40 + kc * 16 + bcol_l) * 2;
            ldsm4(bf[0], bf[1], bf[2], bf[3], ba);
            ldsm4(bf[4], bf[5], bf[6], bf[7], ba + 16 * 40 * 2);
            #pragma unroll
            for (int nt = 0; nt < 4; nt++) {
                mma_f16(c[0][nt], af[0], bf[2 * nt], bf[2 * nt + 1]);
                mma_f16(c[1][nt], af[1], bf[2 * nt], bf[2 * nt + 1]);
            }
        }

        sc = (sc == 2) ? 0 : sc + 1;
        cc = (cc == 2) ? 0 : cc + 1;
    }

    #pragma unroll
    for (int mt = 0; mt < 2; mt++)
        #pragma unroll
        for (int nt = 0; nt < 4; nt++)
            #pragma unroll
            for (int i = 0; i < 4; i++) {
                int m = m0 + wm * 32 + mt * 16 + gq + ((i >= 2) ? 8 : 0);
                int o = o0 + wn * 32 + nt * 8 + 2 * t4 + (i & 1);
                out[(size_t)b * CCH * NT + (size_t)o * NT + m] =
                    c[mt][nt][i] + __ldg(bias + o);
            }
}

// ---------------------------------------------------------------------------
extern "C" void kernel_launch(void* const* d_in, const int* in_sizes, int n_in,
                              void* d_out, int out_size)
{
    (void)in_sizes; (void)n_in; (void)out_size;
    const float* x      = (const float*)d_in[0];
    const float* w_qkv  = (const float*)d_in[1];
    const float* b_qkv  = (const float*)d_in[2];
    const float* w_proj = (const float*)d_in[3];
    const float* b_proj = (const float*)d_in[4];
    float* out = (float*)d_out;

    cudaFuncSetAttribute(qkv_tc_kernel,
                         cudaFuncAttributeMaxDynamicSharedMemorySize,
                         3 * QKV_STAGE_B);
    cudaFuncSetAttribute(attn_mma_kernel,
                         cudaFuncAttributeMaxDynamicSharedMemorySize, ATT_SMEM);
    cudaFuncSetAttribute(proj_tc_kernel,
                         cudaFuncAttributeMaxDynamicSharedMemorySize,
                         3 * PROJ_STAGE_B);

    split_kernel<<<(XN4 + WQ4 + WP4 + 255) / 256, 256>>>(x, w_qkv, w_proj);

    dim3 g1(NT / 128, O3 / 64, BATCH);
    qkv_tc_kernel<<<g1, 256, 3 * QKV_STAGE_B>>>(b_qkv);

    dim3 g2(NT / MT, BATCH * NH);
    attn_mma_kernel<<<g2, 256, ATT_SMEM>>>();

    dim3 g3(NT / 128, CCH / 64, BATCH);
    proj_tc_kernel<<<g3, 256, 3 * PROJ_STAGE_B>>>(b_proj, out);
}